// round 10
// baseline (speedup 1.0000x reference)
#include <cuda_runtime.h>
#include <cstdint>
#include <math.h>

// BaseSmear: project 64^3 grid points into 8 camera images, nearest-neighbor
// gather of 32 feature channels + depth + validity + ray direction.
//
//   1) transpose images [I,C,H,W] -> [I,H,W,C] (channels-last) scratch.
//   2) smear: per-thread projection; cooperative gather via cp.async
//      (8 lanes fetch one pixel's 128B channel vector straight into smem,
//      no register landing -> full MLP); swizzled pixel-major smem,
//      conflict-free scalar LDS + STG.128 streamed output.

#define II 8
#define CC 32
#define HH 240
#define WW 320
#define HW (HH*WW)          // 76800
#define NN (64*64*64)       // 262144
#define NN4 (NN/4)          // 65536

__device__ float g_imgT[(size_t)II * HW * CC];   // 78.6 MB channels-last scratch
__device__ float g_zero[32];                     // 128B zero page (zero-inited)

// ---- Phase 1: [C, HW] -> [HW, C] tile transpose per image ------------------
__global__ __launch_bounds__(256) void transpose_kernel(const float* __restrict__ images) {
    __shared__ float tile[32][33];
    const int tilesPerImg = HW / 32;                 // 2400
    const int i       = blockIdx.x / tilesPerImg;
    const int pixbase = (blockIdx.x % tilesPerImg) * 32;
    const int lane = threadIdx.x & 31;
    const int wy   = threadIdx.x >> 5;               // 0..7

    const float* src = images + (size_t)i * CC * HW + pixbase;
    #pragma unroll
    for (int r = 0; r < 4; r++) {
        const int c = wy + r * 8;
        tile[c][lane] = src[(size_t)c * HW + lane];
    }
    __syncthreads();
    float* dst = g_imgT + ((size_t)i * HW + pixbase) * CC;
    #pragma unroll
    for (int r = 0; r < 4; r++) {
        const int p = wy + r * 8;
        dst[(size_t)p * CC + lane] = tile[lane][p];
    }
}

__device__ __forceinline__ void cp_async16(uint32_t smem_addr, const void* gptr) {
    asm volatile("cp.async.cg.shared.global [%0], [%1], 16;\n"
                 :: "r"(smem_addr), "l"(gptr) : "memory");
}
__device__ __forceinline__ void cp_async_wait_all() {
    asm volatile("cp.async.commit_group;\ncp.async.wait_group 0;\n" ::: "memory");
}

// ---- Phase 2: project + cp.async coop gather + swizzled smem + STG.128 -----
__global__ __launch_bounds__(256, 7) void smear_kernel(
    const float* __restrict__ trans,    // [8,3,4]
    const float* __restrict__ Tcw,      // [8,4,4]
    const float* __restrict__ coords,   // [3,64,64,64]
    float* __restrict__ out)            // [8,37,N] then [3,N]
{
    __shared__ float s[8][32 * 32];     // 4 KB per warp, pixel-major swizzled

    const int tid  = threadIdx.x;
    const int lane = tid & 31;
    const int wrp  = tid >> 5;
    const int bid  = blockIdx.x;
    const int i    = bid >> 10;              // 1024 blocks per image
    const int nb   = (bid & 1023) << 8;      // block's base point
    const int n    = nb + tid;

    // ---------- Phase A: per-thread projection ----------
    const float px = coords[n];
    const float py = coords[NN + n];
    const float pz = coords[2 * NN + n];

    const float* T = Tcw   + i * 16;
    const float* P = trans + i * 12;

    const float depth = T[8] * px + T[9] * py + T[10] * pz + T[11];
    const float w  = P[8] * px + P[9] * py + P[10] * pz + P[11];
    const float ws = (fabsf(w) < 1e-8f) ? 1e-8f : w;
    const float u  = (P[0] * px + P[1] * py + P[2] * pz + P[3]) / ws;
    const float v  = (P[4] * px + P[5] * py + P[6] * pz + P[7]) / ws;

    const bool valid = (u >= 0.0f) && (u <= (float)(WW - 1)) &&
                       (v >= 0.0f) && (v <= (float)(HH - 1)) &&
                       (depth > 0.0f);
    const float validf = valid ? 1.0f : 0.0f;

    const int ui = (int)fminf(fmaxf(rintf(u), 0.0f), (float)(WW - 1));
    const int vi = (int)fminf(fmaxf(rintf(v), 0.0f), (float)(HH - 1));
    const int poffEnc = valid ? (vi * WW + ui) : -1;

    const float ccx = -(T[0] * T[3] + T[4] * T[7] + T[8]  * T[11]);
    const float ccy = -(T[1] * T[3] + T[5] * T[7] + T[9]  * T[11]);
    const float ccz = -(T[2] * T[3] + T[6] * T[7] + T[10] * T[11]);
    float dx = px - ccx, dy = py - ccy, dz = pz - ccz;
    const float inv = 1.0f / (sqrtf(dx * dx + dy * dy + dz * dz) + 1e-8f);

    // extras + coords passthrough: direct streamed stores (coalesced scalar)
    {
        float* eo = out + (size_t)i * 37 * NN + n;
        __stcs(eo + (size_t)32 * NN, depth);
        __stcs(eo + (size_t)33 * NN, validf);
        __stcs(eo + (size_t)34 * NN, dx * inv);
        __stcs(eo + (size_t)35 * NN, dy * inv);
        __stcs(eo + (size_t)36 * NN, dz * inv);
        if (i == 0) {
            float* tail = out + (size_t)II * 37 * NN;
            __stcs(tail + n,          px);
            __stcs(tail + NN + n,     py);
            __stcs(tail + 2 * NN + n, pz);
        }
    }

    // ---------- Phase B: cp.async cooperative gather (8 lanes per pixel) -----
    const int chunk = lane & 7;              // which 16B of the 128B pixel vec
    const int ptoff = lane >> 3;             // which of 4 points this instr

    const float* imgBase = g_imgT + (size_t)i * HW * CC;
    float* sw = s[wrp];
    const uint32_t swAddr = (uint32_t)__cvta_generic_to_shared(sw);

    #pragma unroll
    for (int it = 0; it < 8; it++) {
        const int q  = it * 4 + ptoff;       // point index within warp (0..31)
        const int pe = __shfl_sync(0xffffffffu, poffEnc, q);
        const float* src = (pe >= 0) ? (imgBase + (size_t)pe * CC + chunk * 4)
                                     : (g_zero + chunk * 4);
        // swizzle: 16B group g=chunk stored at g' = chunk ^ (q>>2) = chunk ^ it
        const uint32_t dst = swAddr + (uint32_t)(q * 32 + 4 * (chunk ^ it)) * 4u;
        cp_async16(dst, src);
    }
    cp_async_wait_all();
    __syncwarp();

    // ---------- Phase C: conflict-free scalar LDS + coalesced STG.128 --------
    // warp covers quads (nb>>2) + wrp*8 + 0..7
    float4* o4 = (float4*)out + (size_t)i * 37 * NN4 + (nb >> 2) + wrp * 8;
    const int qq = lane & 7;                 // quad within warp
    const int c3 = lane >> 3;                // c & 3

    #pragma unroll
    for (int r = 0; r < 8; r++) {
        const int c = r * 4 + c3;            // channel 0..31 (c>>2 == r)
        // word(q, c) = q*32 + 4*((c>>2)^(q>>2)) + (c&3), q = 4*qq + j
        const int off = 4 * (r ^ qq) + c3;
        float4 val;
        val.x = sw[(4 * qq + 0) * 32 + off];
        val.y = sw[(4 * qq + 1) * 32 + off];
        val.z = sw[(4 * qq + 2) * 32 + off];
        val.w = sw[(4 * qq + 3) * 32 + off];
        __stcs(&o4[(size_t)c * NN4 + qq], val);
    }
}

extern "C" void kernel_launch(void* const* d_in, const int* in_sizes, int n_in,
                              void* d_out, int out_size) {
    const float* images = (const float*)d_in[0];
    const float* trans  = (const float*)d_in[1];
    const float* Tcw    = (const float*)d_in[2];
    const float* coords = (const float*)d_in[3];
    float* out = (float*)d_out;

    transpose_kernel<<<II * (HW / 32), 256>>>(images);
    smear_kernel<<<II * (NN / 256), 256>>>(trans, Tcw, coords, out);
}

// round 11
// speedup vs baseline: 1.3195x; 1.3195x over previous
#include <cuda_runtime.h>
#include <cstdint>
#include <math.h>

// BaseSmear: project 64^3 grid points into 8 camera images, nearest-neighbor
// gather of 32 feature channels + depth + validity + ray direction.
//
//   1) transpose images [I,C,H,W] -> [I,H,W,C] (channels-last) scratch.
//   2) smear: per-thread projection; cooperative gather (8 lanes share one
//      pixel's 128B channel vector, offsets via SHFL) with ALL 8 LDG.128
//      explicitly hoisted (MLP=8); extras stored inside the latency window;
//      warp-local swizzled smem stage; STG.128 + __stcs streaming output.

#define II 8
#define CC 32
#define HH 240
#define WW 320
#define HW (HH*WW)          // 76800
#define NN (64*64*64)       // 262144
#define NN4 (NN/4)          // 65536

__device__ float g_imgT[(size_t)II * HW * CC];   // 78.6 MB channels-last scratch

// ---- Phase 1: [C, HW] -> [HW, C] tile transpose per image ------------------
__global__ __launch_bounds__(256) void transpose_kernel(const float* __restrict__ images) {
    __shared__ float tile[32][33];
    const int tilesPerImg = HW / 32;                 // 2400
    const int i       = blockIdx.x / tilesPerImg;
    const int pixbase = (blockIdx.x % tilesPerImg) * 32;
    const int lane = threadIdx.x & 31;
    const int wy   = threadIdx.x >> 5;               // 0..7

    const float* src = images + (size_t)i * CC * HW + pixbase;
    #pragma unroll
    for (int r = 0; r < 4; r++) {
        const int c = wy + r * 8;
        tile[c][lane] = src[(size_t)c * HW + lane];
    }
    __syncthreads();
    float* dst = g_imgT + ((size_t)i * HW + pixbase) * CC;
    #pragma unroll
    for (int r = 0; r < 4; r++) {
        const int p = wy + r * 8;
        dst[(size_t)p * CC + lane] = tile[lane][p];
    }
}

// ---- Phase 2: project + MLP-8 coop gather + warp-local stage + STG.128 -----
__global__ __launch_bounds__(256, 4) void smear_kernel(
    const float* __restrict__ trans,    // [8,3,4]
    const float* __restrict__ Tcw,      // [8,4,4]
    const float* __restrict__ coords,   // [3,64,64,64]
    float* __restrict__ out)            // [8,37,N] then [3,N]
{
    __shared__ float s[8][32 * 32];     // 4 KB per warp, 32 KB total

    const int tid  = threadIdx.x;
    const int lane = tid & 31;
    const int wrp  = tid >> 5;
    const int bid  = blockIdx.x;
    const int i    = bid >> 10;              // 1024 blocks per image
    const int nb   = (bid & 1023) << 8;      // block's base point
    const int n    = nb + tid;

    // ---------- Phase A: per-thread projection ----------
    const float px = coords[n];
    const float py = coords[NN + n];
    const float pz = coords[2 * NN + n];

    const float* T = Tcw   + i * 16;
    const float* P = trans + i * 12;

    const float depth = T[8] * px + T[9] * py + T[10] * pz + T[11];
    const float w  = P[8] * px + P[9] * py + P[10] * pz + P[11];
    const float ws = (fabsf(w) < 1e-8f) ? 1e-8f : w;
    const float u  = (P[0] * px + P[1] * py + P[2] * pz + P[3]) / ws;
    const float v  = (P[4] * px + P[5] * py + P[6] * pz + P[7]) / ws;

    const bool valid = (u >= 0.0f) && (u <= (float)(WW - 1)) &&
                       (v >= 0.0f) && (v <= (float)(HH - 1)) &&
                       (depth > 0.0f);
    const float validf = valid ? 1.0f : 0.0f;

    const int ui = (int)fminf(fmaxf(rintf(u), 0.0f), (float)(WW - 1));
    const int vi = (int)fminf(fmaxf(rintf(v), 0.0f), (float)(HH - 1));
    const int poffEnc = valid ? (vi * WW + ui) : -1;

    // ---------- Phase B1: hoisted cooperative gather (MLP = 8) ----------
    const int chunk = lane & 7;              // which 16B of the 128B pixel vec
    const int ptoff = lane >> 3;             // which of 4 points this instr

    const float* imgBase = g_imgT + (size_t)i * HW * CC + chunk * 4;
    const float4 z4 = make_float4(0.f, 0.f, 0.f, 0.f);

    float4 f[8];
    #pragma unroll
    for (int it = 0; it < 8; it++) {
        const int pe = __shfl_sync(0xffffffffu, poffEnc, it * 4 + ptoff);
        f[it] = z4;
        if (pe >= 0)
            f[it] = __ldg((const float4*)(imgBase + (size_t)pe * CC));
    }

    // ---------- Phase A2: extras + coords (fills the gather latency) --------
    {
        const float ccx = -(T[0] * T[3] + T[4] * T[7] + T[8]  * T[11]);
        const float ccy = -(T[1] * T[3] + T[5] * T[7] + T[9]  * T[11]);
        const float ccz = -(T[2] * T[3] + T[6] * T[7] + T[10] * T[11]);
        float dx = px - ccx, dy = py - ccy, dz = pz - ccz;
        const float inv = 1.0f / (sqrtf(dx * dx + dy * dy + dz * dz) + 1e-8f);

        float* eo = out + (size_t)i * 37 * NN + n;
        __stcs(eo + (size_t)32 * NN, depth);
        __stcs(eo + (size_t)33 * NN, validf);
        __stcs(eo + (size_t)34 * NN, dx * inv);
        __stcs(eo + (size_t)35 * NN, dy * inv);
        __stcs(eo + (size_t)36 * NN, dz * inv);
        if (i == 0) {
            float* tail = out + (size_t)II * 37 * NN;
            __stcs(tail + n,          px);
            __stcs(tail + NN + n,     py);
            __stcs(tail + 2 * NN + n, pz);
        }
    }

    // ---------- Phase B2: drain gathers into warp-local swizzled smem -------
    const int ch = chunk * 4;
    float* sw = s[wrp];
    #pragma unroll
    for (int it = 0; it < 8; it++) {
        const int q = it * 4 + ptoff;        // point index within warp (0..31)
        // swizzle: physical pt = q ^ (ch&28); ch&28 = 4*chunk here
        const int base = ch * 32 + (q ^ (chunk * 4));
        sw[base]      = f[it].x;
        sw[base + 32] = f[it].y;
        sw[base + 64] = f[it].z;
        sw[base + 96] = f[it].w;
    }

    __syncwarp();

    // ---------- Phase C: warp-local coalesced float4 streamed output ----------
    float4* o4 = (float4*)out + (size_t)i * 37 * NN4 + (nb >> 2) + wrp * 8;
    #pragma unroll
    for (int r = 0; r < 8; r++) {
        const int c  = r * 4 + (lane >> 3);  // channel 0..31
        const int qq = lane & 7;             // float4 index within warp (0..7)
        // (qq*4) ^ (c&28): multiple of 4 -> float4 group stays contiguous
        const float4 val = *(const float4*)&sw[c * 32 + ((qq * 4) ^ (c & 28))];
        __stcs(&o4[(size_t)c * NN4 + qq], val);
    }
}

extern "C" void kernel_launch(void* const* d_in, const int* in_sizes, int n_in,
                              void* d_out, int out_size) {
    const float* images = (const float*)d_in[0];
    const float* trans  = (const float*)d_in[1];
    const float* Tcw    = (const float*)d_in[2];
    const float* coords = (const float*)d_in[3];
    float* out = (float*)d_out;

    transpose_kernel<<<II * (HW / 32), 256>>>(images);
    smear_kernel<<<II * (NN / 256), 256>>>(trans, Tcw, coords, out);
}